// round 2
// baseline (speedup 1.0000x reference)
#include <cuda_runtime.h>

// Problem constants (fixed by the dataset)
#define DIMS    768              // D
#define C4      192              // DIMS/4 float4 columns
#define NTOK    128              // tokens per sentence (L/S)
#define CROWS   24               // rows cached fp32 in shared
#define CITER   6                // CROWS / RG
#define DK      96               // query/key dim
#define NTHR    768
#define NWARPS  24
#define RG      4                // row groups (thread t owns rows g, g+4, ...)
#define RPT     32               // rows per thread = NTOK/RG

__global__ __launch_bounds__(NTHR, 2)
void sentence_pool_kernel(const float4* __restrict__ x,
                          const float4* __restrict__ Wq,
                          const float* __restrict__ bq,
                          const float4* __restrict__ Wk,
                          const float* __restrict__ bk,
                          float* __restrict__ out)
{
    extern __shared__ float sm[];
    float4* xsh4 = (float4*)sm;                        // [CROWS*C4] cached rows
    float*  psum = sm + CROWS * DIMS;                  // [RG*DIMS] partial reduce
    float*  xsum = psum + RG * DIMS;                   // [DIMS]
    float*  vsh  = xsum + DIMS;                        // [DIMS]
    float*  ksum = vsh + DIMS;                         // [DK]
    float*  lsh  = ksum + DK;                          // [NTOK]
    float*  red  = lsh + NTOK;                         // [8]

    const int t    = threadIdx.x;
    const int w    = t >> 5;
    const int lane = t & 31;
    const int c4   = t % C4;     // float4 column this thread owns
    const int g    = t / C4;     // row group 0..3
    const float4* xg = x + (size_t)blockIdx.x * (NTOK * C4);

    // ---- Phase A: stream x (float4), cache first CROWS rows, column sums ----
    float4 s4 = make_float4(0.f, 0.f, 0.f, 0.f);
    #pragma unroll
    for (int i = 0; i < RPT; ++i) {
        const int r = g + RG * i;
        float4 v = xg[r * C4 + c4];
        if (i < CITER) xsh4[r * C4 + c4] = v;          // rows 0..CROWS-1
        s4.x += v.x; s4.y += v.y; s4.z += v.z; s4.w += v.w;
    }
    ((float4*)psum)[g * C4 + c4] = s4;
    __syncthreads();
    xsum[t] = psum[0 * DIMS + t] + psum[1 * DIMS + t]
            + psum[2 * DIMS + t] + psum[3 * DIMS + t];
    __syncthreads();

    // ---- Phase B1: ksum = Wk @ xsum + n*bk (24 warps x 4 rows) --------------
    {
        const float4* xsum4 = (const float4*)xsum;
        const int k0 = w * 4;
        const float4* w0 = Wk + (size_t)(k0 + 0) * C4;
        const float4* w1 = Wk + (size_t)(k0 + 1) * C4;
        const float4* w2 = Wk + (size_t)(k0 + 2) * C4;
        const float4* w3 = Wk + (size_t)(k0 + 3) * C4;
        float a0 = 0.f, a1 = 0.f, a2 = 0.f, a3 = 0.f;
        #pragma unroll
        for (int j = 0; j < C4 / 32; ++j) {
            const int d = j * 32 + lane;
            float4 xv = xsum4[d];
            float4 q;
            q = w0[d]; a0 += q.x*xv.x + q.y*xv.y + q.z*xv.z + q.w*xv.w;
            q = w1[d]; a1 += q.x*xv.x + q.y*xv.y + q.z*xv.z + q.w*xv.w;
            q = w2[d]; a2 += q.x*xv.x + q.y*xv.y + q.z*xv.z + q.w*xv.w;
            q = w3[d]; a3 += q.x*xv.x + q.y*xv.y + q.z*xv.z + q.w*xv.w;
        }
        #pragma unroll
        for (int off = 16; off; off >>= 1) {
            a0 += __shfl_down_sync(0xffffffffu, a0, off);
            a1 += __shfl_down_sync(0xffffffffu, a1, off);
            a2 += __shfl_down_sync(0xffffffffu, a2, off);
            a3 += __shfl_down_sync(0xffffffffu, a3, off);
        }
        if (lane == 0) {
            ksum[k0 + 0] = a0 + (float)NTOK * bk[k0 + 0];
            ksum[k0 + 1] = a1 + (float)NTOK * bk[k0 + 1];
            ksum[k0 + 2] = a2 + (float)NTOK * bk[k0 + 2];
            ksum[k0 + 3] = a3 + (float)NTOK * bk[k0 + 3];
        }
    }
    __syncthreads();

    // ---- Phase B2: v = Wq^T @ ksum (split DK over the 4 row groups) ---------
    {
        float4 a = make_float4(0.f, 0.f, 0.f, 0.f);
        const int kbeg = g * (DK / RG);
        #pragma unroll
        for (int kk = 0; kk < DK / RG; ++kk) {
            const int k = kbeg + kk;
            const float kv = ksum[k];
            float4 q = Wq[(size_t)k * C4 + c4];
            a.x += kv * q.x; a.y += kv * q.y; a.z += kv * q.z; a.w += kv * q.w;
        }
        ((float4*)psum)[g * C4 + c4] = a;
    }
    __syncthreads();
    vsh[t] = psum[0 * DIMS + t] + psum[1 * DIMS + t]
           + psum[2 * DIMS + t] + psum[3 * DIMS + t];
    // bq . ksum is constant across tokens -> softmax-invariant, dropped.
    __syncthreads();

    // ---- Phase C: logits[r] = x_r . v ---------------------------------------
    {
        const float4* vsh4 = (const float4*)vsh;
        for (int r = w; r < NTOK; r += NWARPS) {
            const float4* row = (r < CROWS) ? (xsh4 + r * C4) : (xg + r * C4);
            float a = 0.f;
            #pragma unroll
            for (int j = 0; j < C4 / 32; ++j) {
                const int d = j * 32 + lane;
                float4 xv = row[d], vv = vsh4[d];
                a += xv.x*vv.x + xv.y*vv.y + xv.z*vv.z + xv.w*vv.w;
            }
            #pragma unroll
            for (int off = 16; off; off >>= 1)
                a += __shfl_down_sync(0xffffffffu, a, off);
            if (lane == 0) lsh[r] = a;
        }
    }
    __syncthreads();

    // ---- softmax over 128 logits -------------------------------------------
    float l = (t < NTOK) ? lsh[t] : -3.4e38f;
    if (t < NTOK) {
        float m = l;
        #pragma unroll
        for (int off = 16; off; off >>= 1)
            m = fmaxf(m, __shfl_down_sync(0xffffffffu, m, off));
        if (lane == 0) red[w] = m;                    // warps 0..3 only
    }
    __syncthreads();
    const float mx = fmaxf(fmaxf(red[0], red[1]), fmaxf(red[2], red[3]));
    if (t < NTOK) {
        float e = expf(l - mx);
        lsh[t] = e;
        #pragma unroll
        for (int off = 16; off; off >>= 1)
            e += __shfl_down_sync(0xffffffffu, e, off);
        if (lane == 0) red[4 + w] = e;
    }
    __syncthreads();
    const float inv = 1.0f / (red[4] + red[5] + red[6] + red[7]);

    // ---- Phase D: out = (sum_r e_r * x_r) * inv -----------------------------
    float4 acc = make_float4(0.f, 0.f, 0.f, 0.f);
    #pragma unroll
    for (int i = 0; i < RPT; ++i) {
        const int r = g + RG * i;
        const float e = lsh[r];
        float4 xv = (i < CITER) ? xsh4[r * C4 + c4] : xg[r * C4 + c4];
        acc.x += e * xv.x; acc.y += e * xv.y; acc.z += e * xv.z; acc.w += e * xv.w;
    }
    __syncthreads();   // psum reuse: xsum/vsh reductions long done
    ((float4*)psum)[g * C4 + c4] = acc;
    __syncthreads();
    out[(size_t)blockIdx.x * DIMS + t] =
        (psum[0 * DIMS + t] + psum[1 * DIMS + t]
       + psum[2 * DIMS + t] + psum[3 * DIMS + t]) * inv;
}

extern "C" void kernel_launch(void* const* d_in, const int* in_sizes, int n_in,
                              void* d_out, int out_size)
{
    const float4* x  = (const float4*)d_in[0];
    // d_in[1] = sentence_index (int32) — contiguous equal blocks; unused.
    const float4* Wq = (const float4*)d_in[2];
    const float*  bq = (const float*)d_in[3];
    const float4* Wk = (const float4*)d_in[4];
    const float*  bk = (const float*)d_in[5];
    float* out = (float*)d_out;

    const int smem_bytes =
        (CROWS * DIMS + RG * DIMS + DIMS + DIMS + DK + NTOK + 8) * sizeof(float);
    cudaFuncSetAttribute(sentence_pool_kernel,
                         cudaFuncAttributeMaxDynamicSharedMemorySize, smem_bytes);

    // B*S = 512 sentences, one CTA each; 2 CTAs co-resident per SM.
    sentence_pool_kernel<<<512, NTHR, smem_bytes>>>(x, Wq, bq, Wk, bk, out);
}

// round 3
// speedup vs baseline: 1.4461x; 1.4461x over previous
#include <cuda_runtime.h>

// Problem constants (fixed by the dataset)
#define DIMS    768              // D
#define C4      192              // DIMS/4 float4 columns
#define NTOK    128              // tokens per sentence (L/S)
#define DK      96               // query/key dim
#define NTHR    768
#define RG      4                // row groups; thread t: c4 = t%192, g = t/192
#define TROWS   16               // tile rows for online-softmax pass
#define NTILE   8                // NTOK / TROWS
#define TILE_F4 (TROWS * C4)     // 3072 float4 per tile

__global__ __launch_bounds__(NTHR, 2)
void sentence_pool_kernel(const float4* __restrict__ x,
                          const float4* __restrict__ Wq,
                          const float* __restrict__ bq,
                          const float4* __restrict__ Wk,
                          const float* __restrict__ bk,
                          float* __restrict__ out)
{
    extern __shared__ float sm[];
    float* buf0 = sm;                          // [TILE_F4*4] tile buffer / psum scratch
    float* buf1 = buf0 + TILE_F4 * 4;          // [TILE_F4*4] tile buffer
    float* xsum = buf1 + TILE_F4 * 4;          // [DIMS]
    float* vsh  = xsum + DIMS;                 // [DIMS]
    float* ksum = vsh + DIMS;                  // [DK]
    float* lsh  = ksum + DK;                   // [TROWS] tile logits
    float* swx  = lsh + TROWS;                 // [0..15]=weights [16]=scale [17]=s [18]=m

    const int t    = threadIdx.x;
    const int w    = t >> 5;
    const int lane = t & 31;
    const int c4   = t % C4;
    const int g    = t / C4;
    const float4* xg = x + (size_t)blockIdx.x * (NTOK * C4);

    if (t == 0) { swx[17] = 0.f; swx[18] = -3.4e38f; }

    // ---- Phase A: stream x once -> column sums ------------------------------
    {
        float4 s4 = make_float4(0.f, 0.f, 0.f, 0.f);
        #pragma unroll
        for (int i = 0; i < NTOK / RG; ++i) {
            float4 v = xg[t + NTHR * i];        // row g+4i, column c4
            s4.x += v.x; s4.y += v.y; s4.z += v.z; s4.w += v.w;
        }
        ((float4*)buf0)[t] = s4;
        __syncthreads();
        xsum[t] = buf0[t] + buf0[DIMS + t] + buf0[2 * DIMS + t] + buf0[3 * DIMS + t];
        __syncthreads();
    }

    // ---- Phase B1: ksum = Wk @ xsum + n*bk (24 warps x 4 rows) --------------
    {
        const float4* xsum4 = (const float4*)xsum;
        const int k0 = w * 4;
        const float4* w0 = Wk + (size_t)(k0 + 0) * C4;
        const float4* w1 = Wk + (size_t)(k0 + 1) * C4;
        const float4* w2 = Wk + (size_t)(k0 + 2) * C4;
        const float4* w3 = Wk + (size_t)(k0 + 3) * C4;
        float a0 = 0.f, a1 = 0.f, a2 = 0.f, a3 = 0.f;
        #pragma unroll
        for (int j = 0; j < C4 / 32; ++j) {
            const int d = j * 32 + lane;
            float4 xv = xsum4[d];
            float4 q;
            q = w0[d]; a0 += q.x*xv.x + q.y*xv.y + q.z*xv.z + q.w*xv.w;
            q = w1[d]; a1 += q.x*xv.x + q.y*xv.y + q.z*xv.z + q.w*xv.w;
            q = w2[d]; a2 += q.x*xv.x + q.y*xv.y + q.z*xv.z + q.w*xv.w;
            q = w3[d]; a3 += q.x*xv.x + q.y*xv.y + q.z*xv.z + q.w*xv.w;
        }
        #pragma unroll
        for (int off = 16; off; off >>= 1) {
            a0 += __shfl_down_sync(0xffffffffu, a0, off);
            a1 += __shfl_down_sync(0xffffffffu, a1, off);
            a2 += __shfl_down_sync(0xffffffffu, a2, off);
            a3 += __shfl_down_sync(0xffffffffu, a3, off);
        }
        if (lane == 0) {
            ksum[k0 + 0] = a0 + (float)NTOK * bk[k0 + 0];
            ksum[k0 + 1] = a1 + (float)NTOK * bk[k0 + 1];
            ksum[k0 + 2] = a2 + (float)NTOK * bk[k0 + 2];
            ksum[k0 + 3] = a3 + (float)NTOK * bk[k0 + 3];
        }
    }
    __syncthreads();

    // ---- Phase B2: v = Wq^T @ ksum (DK split over 4 row groups) -------------
    {
        float4 a = make_float4(0.f, 0.f, 0.f, 0.f);
        const int kbeg = g * (DK / RG);
        #pragma unroll
        for (int kk = 0; kk < DK / RG; ++kk) {
            const int k = kbeg + kk;
            const float kv = ksum[k];
            float4 q = Wq[(size_t)k * C4 + c4];
            a.x += kv * q.x; a.y += kv * q.y; a.z += kv * q.z; a.w += kv * q.w;
        }
        ((float4*)buf0)[t] = a;
    }
    __syncthreads();
    vsh[t] = buf0[t] + buf0[DIMS + t] + buf0[2 * DIMS + t] + buf0[3 * DIMS + t];
    // bq . ksum is constant across tokens -> softmax-invariant, dropped.
    __syncthreads();

    // ---- Phase C: second stream of x, tiled online softmax + pooling --------
    // Preload tile 0
    {
        float4* b0 = (float4*)buf0;
        #pragma unroll
        for (int j = 0; j < 4; ++j)
            b0[t + NTHR * j] = xg[t + NTHR * j];
    }
    __syncthreads();

    float4 acc = make_float4(0.f, 0.f, 0.f, 0.f);
    const float4* vsh4 = (const float4*)vsh;

    for (int tt = 0; tt < NTILE; ++tt) {
        float4* cur = (float4*)((tt & 1) ? buf1 : buf0);
        float4* nxt = (float4*)((tt & 1) ? buf0 : buf1);

        // prefetch next tile (all threads)
        if (tt < NTILE - 1) {
            const float4* src = xg + (tt + 1) * TILE_F4;
            #pragma unroll
            for (int j = 0; j < 4; ++j)
                nxt[t + NTHR * j] = src[t + NTHR * j];
        }

        // logits for this tile: warps 0..15, one row each
        if (w < TROWS) {
            float a = 0.f;
            const float4* row = cur + w * C4;
            #pragma unroll
            for (int j = 0; j < C4 / 32; ++j) {
                const int d = j * 32 + lane;
                float4 xv = row[d], vv = vsh4[d];
                a += xv.x*vv.x + xv.y*vv.y + xv.z*vv.z + xv.w*vv.w;
            }
            #pragma unroll
            for (int off = 16; off; off >>= 1)
                a += __shfl_down_sync(0xffffffffu, a, off);
            if (lane == 0) lsh[w] = a;
        }
        __syncthreads();

        // online-softmax bookkeeping: warp 16 only
        if (w == 16) {
            float l = (lane < TROWS) ? lsh[lane] : -3.4e38f;
            float tm = l;
            #pragma unroll
            for (int off = 16; off; off >>= 1)
                tm = fmaxf(tm, __shfl_xor_sync(0xffffffffu, tm, off));
            const float m_old = swx[18];
            const float m_new = fmaxf(m_old, tm);
            const float scale = expf(m_old - m_new);
            float e = (lane < TROWS) ? expf(l - m_new) : 0.f;
            if (lane < TROWS) swx[lane] = e;
            float ts = e;
            #pragma unroll
            for (int off = 16; off; off >>= 1)
                ts += __shfl_xor_sync(0xffffffffu, ts, off);
            if (lane == 0) {
                swx[16] = scale;
                swx[17] = swx[17] * scale + ts;
                swx[18] = m_new;
            }
        }
        __syncthreads();

        // rescale + accumulate this tile (4 rows per thread)
        {
            const float scale = swx[16];
            acc.x *= scale; acc.y *= scale; acc.z *= scale; acc.w *= scale;
            #pragma unroll
            for (int i = 0; i < TROWS / RG; ++i) {
                const int r = g + RG * i;
                const float e = swx[r];
                float4 xv = cur[r * C4 + c4];
                acc.x += e * xv.x; acc.y += e * xv.y;
                acc.z += e * xv.z; acc.w += e * xv.w;
            }
        }
        __syncthreads();   // protects cur before it becomes the next prefetch target
    }

    // ---- final: combine 4 row groups, normalize -----------------------------
    const float inv = 1.0f / swx[17];
    ((float4*)buf0)[t] = acc;
    __syncthreads();
    out[(size_t)blockIdx.x * DIMS + t] =
        (buf0[t] + buf0[DIMS + t] + buf0[2 * DIMS + t] + buf0[3 * DIMS + t]) * inv;
}

extern "C" void kernel_launch(void* const* d_in, const int* in_sizes, int n_in,
                              void* d_out, int out_size)
{
    const float4* x  = (const float4*)d_in[0];
    // d_in[1] = sentence_index (int32) — contiguous equal blocks; unused.
    const float4* Wq = (const float4*)d_in[2];
    const float*  bq = (const float*)d_in[3];
    const float4* Wk = (const float4*)d_in[4];
    const float*  bk = (const float*)d_in[5];
    float* out = (float*)d_out;

    const int smem_bytes =
        (2 * TILE_F4 * 4 + DIMS + DIMS + DK + TROWS + 24) * sizeof(float);
    cudaFuncSetAttribute(sentence_pool_kernel,
                         cudaFuncAttributeMaxDynamicSharedMemorySize, smem_bytes);

    // B*S = 512 sentences, one CTA each; 2 CTAs co-resident per SM.
    sentence_pool_kernel<<<512, NTHR, smem_bytes>>>(x, Wq, bq, Wk, bk, out);
}